// round 10
// baseline (speedup 1.0000x reference)
#include <cuda_runtime.h>
#include <cstdint>

// (B, N, T, H) = (16, 256, 96, 128)
#define BB 16
#define NN 256
#define TT 96
#define HH 128
#define EPS 1e-5f
#define NPAIR (BB * NN)        // 4096
#define G 4                    // pairs per block in the main kernel

// Scratch (static __device__ — allocation-free)
__device__ float g_C[TT * HH];        // time_emb @ W3            (48 KB)
__device__ float g_nodeS[NN * HH];    // node_emb @ W2            (128 KB)
__device__ float g_Wf[TT * HH];       // Wp @ W1  (fused proj)    (48 KB)
__device__ float g_bias[HH];          // bp @ W1 + bf
__device__ float g_A[NPAIR * HH];     // per-pair row: x@Wf + bias + nodeS (2 MB)

// 16-lane-group f32 sum: 4-round shfl butterfly (offsets 1..8 stay inside
// each 16-lane half). redux.sync.add.f32 is NOT available on sm_103a.
__device__ __forceinline__ float group16_sum(float v) {
#pragma unroll
    for (int off = 1; off < 16; off <<= 1)
        v += __shfl_xor_sync(0xffffffffu, v, off);
    return v;
}

// ---------------------------------------------------------------------------
// Prep kernel: tiny GEMMs. 449 blocks x 512 threads, 4-way split-K.
//   r in [0,96)    : g_C[t=r]       = time_emb[r]   @ W3
//   r in [96,192)  : g_Wf[t=r-96]   = Wp[r-96]      @ W1
//   r in [192,448) : g_nodeS[r-192] = node_emb[..]  @ W2
//   r == 448       : g_bias         = bp @ W1 + bf
// ---------------------------------------------------------------------------
__global__ __launch_bounds__(512) void prep_kernel(
    const float* __restrict__ Wp,
    const float* __restrict__ bp,
    const float* __restrict__ Wf,
    const float* __restrict__ bf,
    const float* __restrict__ node_emb,
    const float* __restrict__ time_emb) {

    __shared__ float vsh[HH];
    __shared__ float partial[4][HH];

    const int r = blockIdx.x;
    const int k = threadIdx.x & (HH - 1);
    const int p = threadIdx.x >> 7;       // 0..3

    const float* __restrict__ v;
    const float* __restrict__ W;
    if (r < TT)                { v = time_emb + r * HH;        W = Wf + 2 * HH * HH; }
    else if (r < 2 * TT)       { v = Wp + (r - TT) * HH;       W = Wf; }
    else if (r < 2 * TT + NN)  { v = node_emb + (r - 2*TT)*HH; W = Wf + HH * HH; }
    else                       { v = bp;                       W = Wf; }

    if (threadIdx.x < HH) vsh[threadIdx.x] = v[threadIdx.x];
    __syncthreads();

    float acc = 0.f;
    const int h0 = p * 32;
#pragma unroll
    for (int hh = 0; hh < 32; hh++) {
        const int h = h0 + hh;
        acc += vsh[h] * W[h * HH + k];   // coalesced over k
    }
    partial[p][k] = acc;
    __syncthreads();

    if (threadIdx.x < HH) {
        float s = partial[0][k] + partial[1][k] + partial[2][k] + partial[3][k];
        if (r < TT)               g_C[r * HH + k] = s;
        else if (r < 2 * TT)      g_Wf[(r - TT) * HH + k] = s;
        else if (r < 2 * TT + NN) g_nodeS[(r - 2 * TT) * HH + k] = s;
        else                      g_bias[k] = s + bf[k];
    }
}

// ---------------------------------------------------------------------------
// GEMM-A kernel: g_A[pair,k] = bias[k] + nodeS[pair&255,k]
//                            + sum_t x[pair,t] * Wfused[t,k]
// 256 blocks x 256 threads, 16 pairs per block, register-blocked 8 pairs x
// 1 col per thread. x tile staged TRANSPOSED in smem.
// ---------------------------------------------------------------------------
__global__ __launch_bounds__(256) void gemmA_kernel(const float* __restrict__ x) {
    __shared__ float xsT[TT][16];     // transposed x tile, 6 KB

    const int pair0 = blockIdx.x * 16;
    const int tid   = threadIdx.x;

    for (int idx = tid; idx < 16 * TT; idx += 256) {
        const int pl = idx / TT;
        const int t  = idx - pl * TT;
        xsT[t][pl] = x[(size_t)(pair0 + pl) * TT + t];
    }
    __syncthreads();

    const int k   = tid & (HH - 1);
    const int pl0 = (tid >> 7) * 8;   // 0 or 8

    float acc[8] = {0.f, 0.f, 0.f, 0.f, 0.f, 0.f, 0.f, 0.f};
#pragma unroll 4
    for (int t = 0; t < TT; t++) {
        const float wv = g_Wf[t * HH + k];
        const float4 xa = *reinterpret_cast<const float4*>(&xsT[t][pl0]);
        const float4 xb = *reinterpret_cast<const float4*>(&xsT[t][pl0 + 4]);
        acc[0] += wv * xa.x;  acc[1] += wv * xa.y;
        acc[2] += wv * xa.z;  acc[3] += wv * xa.w;
        acc[4] += wv * xb.x;  acc[5] += wv * xb.y;
        acc[6] += wv * xb.z;  acc[7] += wv * xb.w;
    }

    const float bias = __ldg(g_bias + k);
#pragma unroll
    for (int pl = 0; pl < 8; pl++) {
        const int pair = pair0 + pl0 + pl;
        const int n    = pair & (NN - 1);
        g_A[(size_t)pair * HH + k] = acc[pl] + bias + __ldg(g_nodeS + n * HH + k);
    }
}

// ---------------------------------------------------------------------------
// Main kernel: 1024 blocks x 256 threads, G=4 pairs per block.
// No smem, no __syncthreads. 16 lanes per row, 2 rows per warp per pass.
// Lane il owns cols {4il..+4} and {64+4il..+4}.
// A for all 4 pairs + gamma/beta are REGISTER-resident; each C load (2 f4)
// is reused across the 4 pairs -> per-warp loads:stores ~ 0.21:1, cutting
// L1tex wavefront pressure ~40% vs 1:1. The 4 per-pair shfl chains in a
// pass are independent and interleave. Stores are __stcs (evict-first).
// ---------------------------------------------------------------------------
__global__ __launch_bounds__(256, 3) void gpe_main_kernel(
    const float* __restrict__ gamma,
    const float* __restrict__ beta,
    float* __restrict__ out) {

    const int pair0 = blockIdx.x * G;
    const int tid   = threadIdx.x;
    const int w     = tid >> 5;
    const int l     = tid & 31;
    const int rgrp  = l >> 4;
    const int il    = l & 15;
    const int col0  = 4 * il;
    const int r0    = w * 2 + rgrp;    // base row; passes add 16

    // gamma/beta register-resident
    const float4 gg0 = __ldg(reinterpret_cast<const float4*>(gamma + col0));
    const float4 gg1 = __ldg(reinterpret_cast<const float4*>(gamma + 64 + col0));
    const float4 bb0 = __ldg(reinterpret_cast<const float4*>(beta + col0));
    const float4 bb1 = __ldg(reinterpret_cast<const float4*>(beta + 64 + col0));

    // A slices for all G pairs, register-resident
    float4 a0[G], a1[G];
#pragma unroll
    for (int g = 0; g < G; g++) {
        const float* __restrict__ arow = g_A + (size_t)(pair0 + g) * HH;
        a0[g] = __ldg(reinterpret_cast<const float4*>(arow + col0));
        a1[g] = __ldg(reinterpret_cast<const float4*>(arow + 64 + col0));
    }

#pragma unroll 1
    for (int pass = 0; pass < 6; pass++) {
        const int row = pass * 16 + r0;
        const float* __restrict__ crow = g_C + row * HH;
        const float4 c0 = __ldg(reinterpret_cast<const float4*>(crow + col0));
        const float4 c1 = __ldg(reinterpret_cast<const float4*>(crow + 64 + col0));

#pragma unroll
        for (int g = 0; g < G; g++) {
            float4 v0, v1;
            v0.x = fmaxf(a0[g].x + c0.x, 0.f);
            v0.y = fmaxf(a0[g].y + c0.y, 0.f);
            v0.z = fmaxf(a0[g].z + c0.z, 0.f);
            v0.w = fmaxf(a0[g].w + c0.w, 0.f);
            v1.x = fmaxf(a1[g].x + c1.x, 0.f);
            v1.y = fmaxf(a1[g].y + c1.y, 0.f);
            v1.z = fmaxf(a1[g].z + c1.z, 0.f);
            v1.w = fmaxf(a1[g].w + c1.w, 0.f);

            float s1 = v0.x + v0.y + v0.z + v0.w
                     + v1.x + v1.y + v1.z + v1.w;
            float s2 = v0.x * v0.x + v0.y * v0.y + v0.z * v0.z + v0.w * v0.w
                     + v1.x * v1.x + v1.y * v1.y + v1.z * v1.z + v1.w * v1.w;

            s1 = group16_sum(s1);
            s2 = group16_sum(s2);

            const float mean = s1 * (1.f / HH);
            const float var  = s2 * (1.f / HH) - mean * mean;
            const float rstd = rsqrtf(var + EPS);

            float4 o0, o1;
            o0.x = (v0.x - mean) * rstd * gg0.x + bb0.x;
            o0.y = (v0.y - mean) * rstd * gg0.y + bb0.y;
            o0.z = (v0.z - mean) * rstd * gg0.z + bb0.z;
            o0.w = (v0.w - mean) * rstd * gg0.w + bb0.w;
            o1.x = (v1.x - mean) * rstd * gg1.x + bb1.x;
            o1.y = (v1.y - mean) * rstd * gg1.y + bb1.y;
            o1.z = (v1.z - mean) * rstd * gg1.z + bb1.z;
            o1.w = (v1.w - mean) * rstd * gg1.w + bb1.w;

            float* __restrict__ orow =
                out + ((size_t)(pair0 + g) * TT + row) * HH;
            __stcs(reinterpret_cast<float4*>(orow + col0), o0);
            __stcs(reinterpret_cast<float4*>(orow + 64 + col0), o1);
        }
    }
}

// ---------------------------------------------------------------------------
// Inputs: 0:x 1:Wp 2:bp 3:Wf 4:bf 5:gamma 6:beta 7:node_emb 8:time_emb
// ---------------------------------------------------------------------------
extern "C" void kernel_launch(void* const* d_in, const int* in_sizes, int n_in,
                              void* d_out, int out_size) {
    const float* x        = (const float*)d_in[0];
    const float* Wp       = (const float*)d_in[1];
    const float* bp       = (const float*)d_in[2];
    const float* Wf       = (const float*)d_in[3];
    const float* bf       = (const float*)d_in[4];
    const float* gamma    = (const float*)d_in[5];
    const float* beta     = (const float*)d_in[6];
    const float* node_emb = (const float*)d_in[7];
    const float* time_emb = (const float*)d_in[8];
    float* out = (float*)d_out;

    prep_kernel<<<2 * TT + NN + 1, 512>>>(Wp, bp, Wf, bf, node_emb, time_emb);
    gemmA_kernel<<<NPAIR / 16, 256>>>(x);
    gpe_main_kernel<<<NPAIR / G, 256>>>(gamma, beta, out);
}